// round 7
// baseline (speedup 1.0000x reference)
#include <cuda_runtime.h>
#include <cstdint>

// LocalLayer: y[8192,4096] = x @ W.T + b, W banded. For window group g
// (outs 64g..64g+63) all nonzero W cols lie in [clamp(64g-32,0,3968), +128).
// => one M128 x N64 x K128 tf32 warp-mma GEMM per (row-block, group) CTA.

#define IN_F   4096
#define OUT_F  4096
#define NBATCH 8192
#define BROWS  128
#define KTILE  128
#define NOUT   64
#define NTHR   256

#define PA     132                         // A smem pitch (floats): 33*16B rows -> ldmatrix conflict-free
#define PB     132
#define A_FLOATS (BROWS * PA)              // 16896
#define B_FLOATS (NOUT * PB)               // 8448
#define SMEM_A_OFF 0
#define SMEM_B_OFF (A_FLOATS * 4)          // 67584
#define SMEM_TOTAL ((A_FLOATS + B_FLOATS) * 4)   // 101376
#define YPITCH 68

__device__ __forceinline__ uint32_t smem_u32(const void* p) {
    uint32_t a;
    asm("{ .reg .u64 t; cvta.to.shared.u64 t, %1; cvt.u32.u64 %0, t; }" : "=r"(a) : "l"(p));
    return a;
}
__device__ __forceinline__ uint32_t to_tf32(float f) {
    uint32_t r;
    asm("cvt.rna.tf32.f32 %0, %1;" : "=r"(r) : "f"(f));
    return r;
}
__device__ __forceinline__ void ldsm_x4(uint32_t* r, uint32_t addr) {
    asm volatile("ldmatrix.sync.aligned.m8n8.x4.shared.b16 {%0,%1,%2,%3}, [%4];"
                 : "=r"(r[0]), "=r"(r[1]), "=r"(r[2]), "=r"(r[3]) : "r"(addr));
}
__device__ __forceinline__ void mma_tf32(float* c, const uint32_t* a,
                                         uint32_t b0, uint32_t b1) {
    asm volatile(
        "mma.sync.aligned.m16n8k8.row.col.f32.tf32.tf32.f32 "
        "{%0,%1,%2,%3}, {%4,%5,%6,%7}, {%8,%9}, {%0,%1,%2,%3};"
        : "+f"(c[0]), "+f"(c[1]), "+f"(c[2]), "+f"(c[3])
        : "r"(a[0]), "r"(a[1]), "r"(a[2]), "r"(a[3]), "r"(b0), "r"(b1));
}
__device__ __forceinline__ int clampi(int v, int lo, int hi) {
    return v < lo ? lo : (v > hi ? hi : v);
}

extern "C" __global__ void __launch_bounds__(NTHR, 2)
local_layer_mma_kernel(const float* __restrict__ x,
                       const float* __restrict__ W,
                       const float* __restrict__ b,
                       float* __restrict__ y)
{
    extern __shared__ float smem[];
    float* As = smem;                        // [128][PA] tf32 bits
    float* Bs = smem + A_FLOATS;             // [64][PB]

    const int rb = blockIdx.x;               // 64 row blocks
    const int g  = blockIdx.y;               // 64 window groups
    const int rbase = rb * BROWS;
    const int jbp = clampi(64 * g - 32, 0, IN_F - KTILE);

    const int tid = threadIdx.x;

    // ---- stage A = x[rbase..+128][jbp..+128) as tf32 ----
    #pragma unroll
    for (int i = 0; i < 16; i++) {
        int idx = tid + NTHR * i;            // 0..4095
        int row = idx >> 5;
        int c4  = idx & 31;
        const float4 v = *(const float4*)(x + (size_t)(rbase + row) * IN_F + jbp + 4 * c4);
        uint4 t;
        t.x = to_tf32(v.x); t.y = to_tf32(v.y); t.z = to_tf32(v.z); t.w = to_tf32(v.w);
        *(uint4*)(As + row * PA + 4 * c4) = t;
    }
    // ---- stage B = W[64g..+64][jbp..+128) as tf32 ----
    #pragma unroll
    for (int i = 0; i < 8; i++) {
        int idx = tid + NTHR * i;            // 0..2047
        int row = idx >> 5;                  // 0..63
        int c4  = idx & 31;
        const float4 v = *(const float4*)(W + (size_t)(64 * g + row) * IN_F + jbp + 4 * c4);
        uint4 t;
        t.x = to_tf32(v.x); t.y = to_tf32(v.y); t.z = to_tf32(v.z); t.w = to_tf32(v.w);
        *(uint4*)(Bs + row * PB + 4 * c4) = t;
    }
    __syncthreads();

    // ---- mainloop: warp tile M32 x N32, K=128 in 16 k8-steps ----
    const int w    = tid >> 5;
    const int lane = tid & 31;
    const int mrow  = (w & 3) * 32;
    const int nbase = (w >> 2) * 32;

    const int q  = lane >> 3;                // ldmatrix sub-matrix id
    const int lr = lane & 7;                 // ldmatrix row

    // A ldmatrix base (per mt): matrix q -> rowblock q&1, colblock q>>1
    uint32_t a_addr[2], b_addr[2];
    #pragma unroll
    for (int mt = 0; mt < 2; mt++) {
        int arow = mrow + mt * 16 + (q & 1) * 8 + lr;
        int acol = (q >> 1) * 4;
        a_addr[mt] = smem_u32(As + arow * PA + acol);
    }
    // B ldmatrix base (per nb=16-out halves): matrix q -> n-subtile q>>1, colblock q&1
    #pragma unroll
    for (int nb = 0; nb < 2; nb++) {
        int brow = nbase + nb * 16 + (q >> 1) * 8 + lr;
        int bcol = (q & 1) * 4;
        b_addr[nb] = smem_u32(Bs + brow * PB + bcol);
    }

    float acc[2][4][4];
    #pragma unroll
    for (int mt = 0; mt < 2; mt++)
        #pragma unroll
        for (int nt = 0; nt < 4; nt++)
            #pragma unroll
            for (int c = 0; c < 4; c++) acc[mt][nt][c] = 0.0f;

    uint32_t afr[2][2][4], bfr[2][2][4];
    // preload ks=0
    ldsm_x4(afr[0][0], a_addr[0]);
    ldsm_x4(afr[0][1], a_addr[1]);
    ldsm_x4(bfr[0][0], b_addr[0]);
    ldsm_x4(bfr[0][1], b_addr[1]);

    #pragma unroll
    for (int ks = 0; ks < 16; ks++) {
        const int cur = ks & 1;
        const int nxt = cur ^ 1;
        const int ksn = (ks + 1) & 15;
        // prefetch next k-step fragments
        ldsm_x4(afr[nxt][0], a_addr[0] + ksn * 32);
        ldsm_x4(afr[nxt][1], a_addr[1] + ksn * 32);
        ldsm_x4(bfr[nxt][0], b_addr[0] + ksn * 32);
        ldsm_x4(bfr[nxt][1], b_addr[1] + ksn * 32);

        #pragma unroll
        for (int mt = 0; mt < 2; mt++)
            #pragma unroll
            for (int nt = 0; nt < 4; nt++) {
                const int nb = nt >> 1, sel = nt & 1;
                mma_tf32(acc[mt][nt], afr[cur][mt],
                         bfr[cur][nb][2 * sel], bfr[cur][nb][2 * sel + 1]);
            }
    }

    // ---- epilogue: regs -> ys smem (transpose) -> coalesced STG + bias ----
    __syncthreads();
    float* ys = smem;                        // [128][YPITCH]
    const int gg = lane >> 2;
    const int tt = lane & 3;

    #pragma unroll
    for (int mt = 0; mt < 2; mt++)
        #pragma unroll
        for (int nt = 0; nt < 4; nt++) {
            const float* c = acc[mt][nt];
            int col = nbase + nt * 8 + 2 * tt;
            int r0  = mrow + mt * 16 + gg;
            *(float2*)(ys + r0 * YPITCH + col)       = make_float2(c[0], c[1]);
            *(float2*)(ys + (r0 + 8) * YPITCH + col) = make_float2(c[2], c[3]);
        }
    __syncthreads();

    {
        const float4 bv = *(const float4*)(b + 64 * g + 4 * (tid & 15));
        #pragma unroll
        for (int i = 0; i < 8; i++) {
            int idx = tid + NTHR * i;        // 0..2047
            int row = idx >> 4;
            int c4  = idx & 15;
            float4 v = *(const float4*)(ys + row * YPITCH + 4 * c4);
            v.x += bv.x; v.y += bv.y; v.z += bv.z; v.w += bv.w;
            *(float4*)(y + (size_t)(rbase + row) * OUT_F + 64 * g + 4 * c4) = v;
        }
    }
}

extern "C" void kernel_launch(void* const* d_in, const int* in_sizes, int n_in,
                              void* d_out, int out_size) {
    const float* x = (const float*)d_in[0];
    const float* W = (const float*)d_in[1];
    const float* b = (const float*)d_in[2];
    // d_in[3] = mask, unused (already baked into W at init)
    float* y = (float*)d_out;

    cudaFuncSetAttribute(local_layer_mma_kernel,
                         cudaFuncAttributeMaxDynamicSharedMemorySize, SMEM_TOTAL);

    dim3 grid(NBATCH / BROWS, OUT_F / NOUT);   // 64 x 64
    local_layer_mma_kernel<<<grid, NTHR, SMEM_TOTAL>>>(x, W, b, y);
}

// round 8
// speedup vs baseline: 1.3418x; 1.3418x over previous
#include <cuda_runtime.h>
#include <cstdint>

// LocalLayer: y[8192,4096] = x @ W.T + b, W banded. For window group g
// (outs 64g..64g+63) all nonzero W cols lie in [clamp(64g-32,0,3968), +128).
// CTA: fixed g, 4 M64 row-tiles chained; tf32 mma.sync; cp.async pipelined A.

#define IN_F   4096
#define OUT_F  4096
#define NBATCH 8192
#define KTILE  128
#define KH     64          // K half per pipeline stage
#define MTILE  64
#define CHUNK  4           // tiles per CTA
#define NTHR   256

#define PB     132         // B smem pitch (floats)
#define PH     68          // A half-buffer pitch (floats)
#define B_FLOATS   (64 * PB)          // 8448
#define ABUF_FLOATS (64 * PH)         // 4352
#define SMEM_FLOATS (B_FLOATS + 2 * ABUF_FLOATS)   // 17152
#define SMEM_TOTAL  (SMEM_FLOATS * 4)              // 68608 B -> 3 CTAs/SM

__device__ __forceinline__ uint32_t smem_u32(const void* p) {
    uint32_t a;
    asm("{ .reg .u64 t; cvta.to.shared.u64 t, %1; cvt.u32.u64 %0, t; }" : "=r"(a) : "l"(p));
    return a;
}
__device__ __forceinline__ uint32_t to_tf32(float f) {
    uint32_t r;
    asm("cvt.rna.tf32.f32 %0, %1;" : "=r"(r) : "f"(f));
    return r;
}
__device__ __forceinline__ void ldsm_x4(uint32_t* r, uint32_t addr) {
    asm volatile("ldmatrix.sync.aligned.m8n8.x4.shared.b16 {%0,%1,%2,%3}, [%4];"
                 : "=r"(r[0]), "=r"(r[1]), "=r"(r[2]), "=r"(r[3]) : "r"(addr));
}
__device__ __forceinline__ void mma_tf32(float* c, const uint32_t* a,
                                         uint32_t b0, uint32_t b1) {
    asm volatile(
        "mma.sync.aligned.m16n8k8.row.col.f32.tf32.tf32.f32 "
        "{%0,%1,%2,%3}, {%4,%5,%6,%7}, {%8,%9}, {%0,%1,%2,%3};"
        : "+f"(c[0]), "+f"(c[1]), "+f"(c[2]), "+f"(c[3])
        : "r"(a[0]), "r"(a[1]), "r"(a[2]), "r"(a[3]), "r"(b0), "r"(b1));
}
__device__ __forceinline__ void cp_async16(uint32_t dst, const void* src) {
    asm volatile("cp.async.cg.shared.global [%0], [%1], 16;" :: "r"(dst), "l"(src));
}
__device__ __forceinline__ int clampi(int v, int lo, int hi) {
    return v < lo ? lo : (v > hi ? hi : v);
}

extern "C" __global__ void __launch_bounds__(NTHR, 3)
local_layer_mma_pipe(const float* __restrict__ x,
                     const float* __restrict__ W,
                     const float* __restrict__ b,
                     float* __restrict__ y)
{
    extern __shared__ float smem[];
    float* Bs = smem;                          // [64][PB] tf32 bits
    float* Ab[2] = { smem + B_FLOATS, smem + B_FLOATS + ABUF_FLOATS };

    const int g  = blockIdx.y;                 // 64 groups
    const int cm = blockIdx.x;                 // 32 row chunks (256 rows each)
    const int rbase0 = cm * (MTILE * CHUNK);
    const int jbp = clampi(64 * g - 32, 0, IN_F - KTILE);

    const int tid  = threadIdx.x;
    const int w    = tid >> 5;
    const int lane = tid & 31;

    // ---- stage B = W[64g..+64][jbp..+128) as tf32 (once per CTA) ----
    #pragma unroll
    for (int i = 0; i < 8; i++) {
        int idx = tid + NTHR * i;              // 0..2047
        int row = idx >> 5;
        int c4  = idx & 31;
        const float4 v = *(const float4*)(W + (size_t)(64 * g + row) * IN_F + jbp + 4 * c4);
        uint4 t;
        t.x = to_tf32(v.x); t.y = to_tf32(v.y); t.z = to_tf32(v.z); t.w = to_tf32(v.w);
        *(uint4*)(Bs + row * PB + 4 * c4) = t;
    }

    // A stage issue: stage q -> tile q>>1, khalf q&1, buffer q&1
    const int a_row = tid >> 4;                // 0..15 base row block: idx mapping below
    auto issue_stage = [&](int q) {
        const int tile = q >> 1, kh = q & 1;
        const float* src_base = x + (size_t)(rbase0 + tile * MTILE) * IN_F + jbp + kh * KH;
        float* dstb = Ab[q & 1];
        #pragma unroll
        for (int i = 0; i < 4; i++) {
            int idx = tid + NTHR * i;          // 0..1023
            int row = idx >> 4;                // 0..63
            int c4  = idx & 15;                // 0..15
            cp_async16(smem_u32(dstb + row * PH + 4 * c4),
                       src_base + (size_t)row * IN_F + 4 * c4);
        }
    };
    (void)a_row;

    issue_stage(0);
    asm volatile("cp.async.commit_group;" ::: "memory");
    issue_stage(1);
    asm volatile("cp.async.commit_group;" ::: "memory");

    // ---- warp mapping: warp tile M16 x N32 ----
    const int mrow  = (w & 3) * 16;
    const int nbase = (w >> 2) * 32;
    const int q_  = lane >> 3;
    const int lr  = lane & 7;
    const int gg  = lane >> 2;
    const int tt  = lane & 3;

    uint32_t a_base[2];
    #pragma unroll
    for (int bufi = 0; bufi < 2; bufi++)
        a_base[bufi] = smem_u32(Ab[bufi] + (mrow + (q_ & 1) * 8 + lr) * PH + (q_ >> 1) * 4);
    uint32_t b_addr[2];
    #pragma unroll
    for (int nb = 0; nb < 2; nb++)
        b_addr[nb] = smem_u32(Bs + (nbase + nb * 16 + (q_ >> 1) * 8 + lr) * PB + (q_ & 1) * 4);

    // bias per lane (float2 per nt)
    float2 bias[4];
    #pragma unroll
    for (int nt = 0; nt < 4; nt++)
        bias[nt] = *(const float2*)(b + 64 * g + nbase + nt * 8 + 2 * tt);

    float acc[4][4];
    #pragma unroll
    for (int nt = 0; nt < 4; nt++)
        #pragma unroll
        for (int c = 0; c < 4; c++) acc[nt][c] = 0.0f;

    #pragma unroll
    for (int q = 0; q < 2 * CHUNK; q++) {
        asm volatile("cp.async.wait_group 1;" ::: "memory");
        __syncthreads();

        const int kh  = q & 1;
        const int buf = q & 1;

        #pragma unroll
        for (int ks = 0; ks < 8; ks++) {
            uint32_t ar[4], af[4], bf0[4], bf1[4];
            ldsm_x4(ar,  a_base[buf] + ks * 32);
            ldsm_x4(bf0, b_addr[0] + (kh * 8 + ks) * 32);
            ldsm_x4(bf1, b_addr[1] + (kh * 8 + ks) * 32);
            #pragma unroll
            for (int i = 0; i < 4; i++) af[i] = to_tf32(__uint_as_float(ar[i]));
            mma_tf32(acc[0], af, bf0[0], bf0[1]);
            mma_tf32(acc[1], af, bf0[2], bf0[3]);
            mma_tf32(acc[2], af, bf1[0], bf1[1]);
            mma_tf32(acc[3], af, bf1[2], bf1[3]);
        }

        if (kh == 1) {
            // epilogue for tile q>>1: direct STG.64 with bias
            const int r0 = rbase0 + (q >> 1) * MTILE + mrow + gg;
            #pragma unroll
            for (int nt = 0; nt < 4; nt++) {
                const int gcol = 64 * g + nbase + nt * 8 + 2 * tt;
                *(float2*)(y + (size_t)r0 * OUT_F + gcol) =
                    make_float2(acc[nt][0] + bias[nt].x, acc[nt][1] + bias[nt].y);
                *(float2*)(y + (size_t)(r0 + 8) * OUT_F + gcol) =
                    make_float2(acc[nt][2] + bias[nt].x, acc[nt][3] + bias[nt].y);
                #pragma unroll
                for (int c = 0; c < 4; c++) acc[nt][c] = 0.0f;
            }
        }
        __syncthreads();

        if (q + 2 < 2 * CHUNK) issue_stage(q + 2);
        asm volatile("cp.async.commit_group;" ::: "memory");
    }
}

extern "C" void kernel_launch(void* const* d_in, const int* in_sizes, int n_in,
                              void* d_out, int out_size) {
    const float* x = (const float*)d_in[0];
    const float* W = (const float*)d_in[1];
    const float* b = (const float*)d_in[2];
    // d_in[3] = mask, unused (already baked into W at init)
    float* y = (float*)d_out;

    cudaFuncSetAttribute(local_layer_mma_pipe,
                         cudaFuncAttributeMaxDynamicSharedMemorySize, SMEM_TOTAL);

    dim3 grid(NBATCH / (MTILE * CHUNK), OUT_F / 64);   // 32 x 64
    local_layer_mma_pipe<<<grid, NTHR, SMEM_TOTAL>>>(x, W, b, y);
}

// round 10
// speedup vs baseline: 1.4856x; 1.1072x over previous
#include <cuda_runtime.h>
#include <cstdint>

// LocalLayer: y[8192,4096] = x @ W.T + b, W banded. For window group g
// (outs 64g..64g+63) all nonzero W cols lie in [clamp(64g-32,0,3968), +128).
// CTA: fixed g, M128xN64xK128 tiles (2 chained); warp tile M32xN32;
// tf32 mma.sync; cp.async double-buffered A staging at K=32 granularity.

#define IN_F   4096
#define OUT_F  4096
#define NBATCH 8192
#define KTILE  128
#define KH     32          // K quarter per pipeline stage
#define MTILE  128
#define CHUNK  2           // tiles per CTA
#define NTHR   256

#define PB     132         // B smem pitch (floats): rows hold 128 floats; 528B stride conflict-free
#define PA     36          // A buf pitch (floats): rows hold 32 floats; 144B stride conflict-free
#define B_FLOATS    (64 * PB)          // 8448
#define ABUF_FLOATS (MTILE * PA)       // 4608
#define SMEM_FLOATS (B_FLOATS + 2 * ABUF_FLOATS)   // 17664
#define SMEM_TOTAL  (SMEM_FLOATS * 4)              // 70656 B -> 3 CTAs/SM

__device__ __forceinline__ uint32_t smem_u32(const void* p) {
    uint32_t a;
    asm("{ .reg .u64 t; cvta.to.shared.u64 t, %1; cvt.u32.u64 %0, t; }" : "=r"(a) : "l"(p));
    return a;
}
__device__ __forceinline__ uint32_t to_tf32(float f) {
    uint32_t r;
    asm("cvt.rna.tf32.f32 %0, %1;" : "=r"(r) : "f"(f));
    return r;
}
__device__ __forceinline__ void ldsm_x4(uint32_t* r, uint32_t addr) {
    asm volatile("ldmatrix.sync.aligned.m8n8.x4.shared.b16 {%0,%1,%2,%3}, [%4];"
                 : "=r"(r[0]), "=r"(r[1]), "=r"(r[2]), "=r"(r[3]) : "r"(addr));
}
__device__ __forceinline__ void mma_tf32(float* c, const uint32_t* a,
                                         uint32_t b0, uint32_t b1) {
    asm volatile(
        "mma.sync.aligned.m16n8k8.row.col.f32.tf32.tf32.f32 "
        "{%0,%1,%2,%3}, {%4,%5,%6,%7}, {%8,%9}, {%0,%1,%2,%3};"
        : "+f"(c[0]), "+f"(c[1]), "+f"(c[2]), "+f"(c[3])
        : "r"(a[0]), "r"(a[1]), "r"(a[2]), "r"(a[3]), "r"(b0), "r"(b1));
}
__device__ __forceinline__ void cp_async16(uint32_t dst, const void* src) {
    asm volatile("cp.async.cg.shared.global [%0], [%1], 16;" :: "r"(dst), "l"(src));
}
__device__ __forceinline__ int clampi(int v, int lo, int hi) {
    return v < lo ? lo : (v > hi ? hi : v);
}

extern "C" __global__ void __launch_bounds__(NTHR, 3)
local_layer_mma_pipe2(const float* __restrict__ x,
                      const float* __restrict__ W,
                      const float* __restrict__ b,
                      float* __restrict__ y)
{
    extern __shared__ float smem[];
    float* Bs = smem;                          // [64][PB] tf32 bits
    float* Ab[2] = { smem + B_FLOATS, smem + B_FLOATS + ABUF_FLOATS };

    const int g  = blockIdx.y;                 // 64 groups
    const int cm = blockIdx.x;                 // 32 row chunks (256 rows each)
    const int rbase0 = cm * (MTILE * CHUNK);
    const int jbp = clampi(64 * g - 32, 0, IN_F - KTILE);

    const int tid  = threadIdx.x;
    const int w    = tid >> 5;
    const int lane = tid & 31;

    // ---- stage B = W[64g..+64][jbp..+128) as tf32 (once per CTA) ----
    #pragma unroll
    for (int i = 0; i < 8; i++) {
        int idx = tid + NTHR * i;              // 0..2047
        int row = idx >> 5;
        int c4  = idx & 31;
        const float4 v = *(const float4*)(W + (size_t)(64 * g + row) * IN_F + jbp + 4 * c4);
        uint4 t;
        t.x = to_tf32(v.x); t.y = to_tf32(v.y); t.z = to_tf32(v.z); t.w = to_tf32(v.w);
        *(uint4*)(Bs + row * PB + 4 * c4) = t;
    }

    // A stage issue: stage q -> tile q>>2, kquarter q&3, buffer q&1
    auto issue_stage = [&](int q) {
        const int tile = q >> 2, kh = q & 3;
        const float* src_base = x + (size_t)(rbase0 + tile * MTILE) * IN_F + jbp + kh * KH;
        float* dstb = Ab[q & 1];
        #pragma unroll
        for (int i = 0; i < 4; i++) {
            int idx = tid + NTHR * i;          // 0..1023
            int row = idx >> 3;                // 0..127
            int c4  = idx & 7;                 // 0..7 (32 floats per row)
            cp_async16(smem_u32(dstb + row * PA + 4 * c4),
                       src_base + (size_t)row * IN_F + 4 * c4);
        }
    };

    issue_stage(0);
    asm volatile("cp.async.commit_group;" ::: "memory");
    issue_stage(1);
    asm volatile("cp.async.commit_group;" ::: "memory");

    // ---- warp mapping: 4x2 grid of M32 x N32 warp tiles ----
    const int mrow  = (w & 3) * 32;
    const int nbase = (w >> 2) * 32;
    const int q_  = lane >> 3;
    const int lr  = lane & 7;
    const int gg  = lane >> 2;
    const int tt  = lane & 3;

    uint32_t a_base[2][2];                     // [buf][mt]
    #pragma unroll
    for (int bufi = 0; bufi < 2; bufi++)
        #pragma unroll
        for (int mt = 0; mt < 2; mt++)
            a_base[bufi][mt] = smem_u32(Ab[bufi]
                + (mrow + mt * 16 + (q_ & 1) * 8 + lr) * PA + (q_ >> 1) * 4);
    uint32_t b_addr[2];
    #pragma unroll
    for (int nb = 0; nb < 2; nb++)
        b_addr[nb] = smem_u32(Bs + (nbase + nb * 16 + (q_ >> 1) * 8 + lr) * PB + (q_ & 1) * 4);

    float2 bias[4];
    #pragma unroll
    for (int nt = 0; nt < 4; nt++)
        bias[nt] = *(const float2*)(b + 64 * g + nbase + nt * 8 + 2 * tt);

    float acc[2][4][4];
    #pragma unroll
    for (int mt = 0; mt < 2; mt++)
        #pragma unroll
        for (int nt = 0; nt < 4; nt++)
            #pragma unroll
            for (int c = 0; c < 4; c++) acc[mt][nt][c] = 0.0f;

    #pragma unroll
    for (int s = 0; s < 4 * CHUNK; s++) {
        asm volatile("cp.async.wait_group 1;" ::: "memory");
        __syncthreads();

        const int kh  = s & 3;
        const int buf = s & 1;

        #pragma unroll
        for (int ks = 0; ks < 4; ks++) {       // K8 steps within KH=32
            uint32_t ar0[4], ar1[4], af0[4], af1[4], bf0[4], bf1[4];
            ldsm_x4(ar0, a_base[buf][0] + ks * 32);
            ldsm_x4(ar1, a_base[buf][1] + ks * 32);
            ldsm_x4(bf0, b_addr[0] + kh * 128 + ks * 32);
            ldsm_x4(bf1, b_addr[1] + kh * 128 + ks * 32);
            #pragma unroll
            for (int i = 0; i < 4; i++) {
                af0[i] = to_tf32(__uint_as_float(ar0[i]));
                af1[i] = to_tf32(__uint_as_float(ar1[i]));
            }
            mma_tf32(acc[0][0], af0, bf0[0], bf0[1]);
            mma_tf32(acc[0][1], af0, bf0[2], bf0[3]);
            mma_tf32(acc[0][2], af0, bf1[0], bf1[1]);
            mma_tf32(acc[0][3], af0, bf1[2], bf1[3]);
            mma_tf32(acc[1][0], af1, bf0[0], bf0[1]);
            mma_tf32(acc[1][1], af1, bf0[2], bf0[3]);
            mma_tf32(acc[1][2], af1, bf1[0], bf1[1]);
            mma_tf32(acc[1][3], af1, bf1[2], bf1[3]);
        }

        if (kh == 3) {
            // epilogue for tile s>>2: direct STG.64 with bias
            const int tile = s >> 2;
            #pragma unroll
            for (int mt = 0; mt < 2; mt++) {
                const int r0 = rbase0 + tile * MTILE + mrow + mt * 16 + gg;
                #pragma unroll
                for (int nt = 0; nt < 4; nt++) {
                    const int gcol = 64 * g + nbase + nt * 8 + 2 * tt;
                    float* c = acc[mt][nt];
                    *(float2*)(y + (size_t)r0 * OUT_F + gcol) =
                        make_float2(c[0] + bias[nt].x, c[1] + bias[nt].y);
                    *(float2*)(y + (size_t)(r0 + 8) * OUT_F + gcol) =
                        make_float2(c[2] + bias[nt].x, c[3] + bias[nt].y);
                    #pragma unroll
                    for (int cc = 0; cc < 4; cc++) c[cc] = 0.0f;
                }
            }
        }
        __syncthreads();

        if (s + 2 < 4 * CHUNK) issue_stage(s + 2);
        asm volatile("cp.async.commit_group;" ::: "memory");
    }
}

extern "C" void kernel_launch(void* const* d_in, const int* in_sizes, int n_in,
                              void* d_out, int out_size) {
    const float* x = (const float*)d_in[0];
    const float* W = (const float*)d_in[1];
    const float* b = (const float*)d_in[2];
    // d_in[3] = mask, unused (already baked into W at init)
    float* y = (float*)d_out;

    cudaFuncSetAttribute(local_layer_mma_pipe2,
                         cudaFuncAttributeMaxDynamicSharedMemorySize, SMEM_TOTAL);

    dim3 grid(NBATCH / (MTILE * CHUNK), OUT_F / 64);   // 32 x 64
    local_layer_mma_pipe2<<<grid, NTHR, SMEM_TOTAL>>>(x, W, b, y);
}